// round 4
// baseline (speedup 1.0000x reference)
#include <cuda_runtime.h>
#include <cuda_bf16.h>
#include <cstdint>

#define Bq 8
#define Nn 2048
#define Dd 128
#define DE 136            // 128 emb + dev + ones + 6 pad -> 17 n8-tiles
#define TM 128
#define TK 32
#define NS 3
#define KSPLIT 2
#define NBLK (Bq * (Nn / TM) * KSPLIT)   // 256

// smem strides (bytes), chosen conflict-free for fp8 fragment LDS patterns
#define A_STRIDE 192      // 128B fp32 data + 64B pad (48 words ≡ 16 mod 32)
#define B_STRIDE 48       // 32B fp8 data + 16B pad  (12 words)
#define A_STAGE  (TM * A_STRIDE)          // 24576
#define B_STAGE  (DE * B_STRIDE)          // 6528
#define STAGE_BYTES (A_STAGE + B_STAGE)   // 31104
#define SMEM_BYTES  (NS * STAGE_BYTES)    // 93312

// scratch (no allocation allowed -> device globals)
__device__ float   g_hsq[Bq * Nn];
__device__ uint8_t g_B8[(size_t)Bq * DE * Nn];   // [b][d][j] e4m3
__device__ float   g_part[NBLK];
__device__ int     g_done;

__device__ __forceinline__ uint32_t smem_u32(const void* p) {
    uint32_t a;
    asm("{ .reg .u64 t; cvta.to.shared.u64 t, %1; cvt.u32.u64 %0, t; }"
        : "=r"(a) : "l"(p));
    return a;
}
__device__ __forceinline__ void cp16(uint32_t dst, const void* src) {
    asm volatile("cp.async.cg.shared.global [%0], [%1], 16;"
                 :: "r"(dst), "l"(src) : "memory");
}
// pack 4 floats -> 4 e4m3 bytes (byte0 = v.x)
__device__ __forceinline__ uint32_t cvt4_e4m3(float x, float y, float z, float w) {
    uint16_t lo, hi;
    asm("cvt.rn.satfinite.e4m3x2.f32 %0, %1, %2;" : "=h"(lo) : "f"(y), "f"(x));
    asm("cvt.rn.satfinite.e4m3x2.f32 %0, %1, %2;" : "=h"(hi) : "f"(w), "f"(z));
    return (uint32_t)lo | ((uint32_t)hi << 16);
}

// ---------------------------------------------------------------------------
// Kernel 0 (prep): hsq + e4m3 transposed extended embedding
//   B8[b][d][j]:  d<128: h_jd,  d=128: hsq_j-128,  d=129: 1,  d>=130: 0
// ---------------------------------------------------------------------------
__global__ void k_prep(const float* __restrict__ H) {
    __shared__ float s2[32][137];   // odd stride -> conflict-free column reads
    __shared__ float hq[32];
    const int b = blockIdx.y, j0 = blockIdx.x * 32;
    const int tid = threadIdx.x;    // 256
    if (blockIdx.x == 0 && blockIdx.y == 0 && tid == 0) g_done = 0;

    #pragma unroll
    for (int c = 0; c < 4; c++) {
        int idx = tid + c * 256;            // 1024 float4s
        int j = idx >> 5, d4 = (idx & 31) * 4;
        float4 v = *(const float4*)(H + ((size_t)(b * Nn + j0 + j)) * Dd + d4);
        s2[j][d4 + 0] = v.x; s2[j][d4 + 1] = v.y;
        s2[j][d4 + 2] = v.z; s2[j][d4 + 3] = v.w;
    }
    __syncthreads();

    {   // hsq: warp w -> 4 rows, 8 lanes per row
        const int w = tid >> 5, l = tid & 31;
        const int j = w * 4 + (l >> 3), sub = l & 7;
        float sum = 0.f;
        #pragma unroll
        for (int m = 0; m < 16; m++) {
            float v = s2[j][sub + 8 * m];
            sum += v * v;
        }
        sum += __shfl_xor_sync(0xFFFFFFFFu, sum, 1);
        sum += __shfl_xor_sync(0xFFFFFFFFu, sum, 2);
        sum += __shfl_xor_sync(0xFFFFFFFFu, sum, 4);
        if (sub == 0) { hq[j] = sum; g_hsq[b * Nn + j0 + j] = sum; }
    }
    __syncthreads();

    for (int idx = tid; idx < DE * 8; idx += 256) {
        int d = idx >> 3, jq = (idx & 7) * 4;
        float v[4];
        #pragma unroll
        for (int r = 0; r < 4; r++) {
            int j = jq + r;
            v[r] = (d < 128) ? s2[j][d]
                 : (d == 128) ? (hq[j] - 128.0f)
                 : (d == 129) ? 1.0f : 0.0f;
        }
        uint32_t p = cvt4_e4m3(v[0], v[1], v[2], v[3]);
        *(uint32_t*)&g_B8[((size_t)(b * DE + d)) * Nn + j0 + jq] = p;
    }
}

// ---------------------------------------------------------------------------
// Kernel 1: fp8 pipelined GEMM + fused epilogue + last-CTA reduction.
// Grid (KSPLIT, 16, 8). Warps: 4(m) x 2(n); warp tile m32 x n72/n64.
// A: fp32 cp.async -> smem -> LDS.128 + cvt to e4m3 at fragment load.
// ---------------------------------------------------------------------------
__global__ __launch_bounds__(256, 2)
void k_main(const float* __restrict__ A, const float* __restrict__ H,
            float* __restrict__ out) {
    extern __shared__ char smem[];
    __shared__ float s_red[8];
    __shared__ int   s_last;
    const uint32_t sb0 = smem_u32(smem);
    const int tid = threadIdx.x;
    const int wid = tid >> 5, lane = tid & 31;
    const int ks = blockIdx.x, mt = blockIdx.y, b = blockIdx.z;
    const int i0 = mt * TM;
    const int kbase = ks * (Nn / KSPLIT);
    const int NIT = (Nn / KSPLIT) / TK;         // 32

    const int wm = wid >> 1;           // 0..3
    const int wn = wid & 1;            // 0..1
    const int qr = lane >> 2;          // 0..7
    const int qb = (lane & 3) * 16;    // A frag byte offset ((lane&3)*4 floats)
    const int qc = (lane & 3) * 4;     // k offset in elements

    const float*   Ag = A + ((size_t)b * Nn + i0) * Nn + kbase;
    const uint8_t* Bg = g_B8 + ((size_t)b * DE) * Nn + kbase;

    float acc[2][9][4];
    #pragma unroll
    for (int f = 0; f < 2; f++)
        #pragma unroll
        for (int t = 0; t < 9; t++)
            #pragma unroll
            for (int r = 0; r < 4; r++) acc[f][t][r] = 0.f;

    auto issue = [&](int it) {
        uint32_t sa = sb0 + (it % NS) * STAGE_BYTES;
        const float* ag = Ag + it * TK;
        #pragma unroll
        for (int c = 0; c < 4; c++) {
            int e = tid + c * 256;                 // 1024 chunks
            int row = e >> 3, ch = e & 7;
            cp16(sa + row * A_STRIDE + ch * 16, ag + (size_t)row * Nn + ch * 4);
        }
        uint32_t sbB = sa + A_STAGE;
        const uint8_t* bg = Bg + it * TK;
        {
            int row = tid >> 1, ch = tid & 1;      // 256 of 272
            cp16(sbB + row * B_STRIDE + ch * 16, bg + (size_t)row * Nn + ch * 16);
        }
        if (tid < 16) {
            int row = 128 + (tid >> 1), ch = tid & 1;
            cp16(sbB + row * B_STRIDE + ch * 16, bg + (size_t)row * Nn + ch * 16);
        }
    };

    // prologue: stages 0..NS-2
    #pragma unroll
    for (int p = 0; p < NS - 1; p++) {
        issue(p);
        asm volatile("cp.async.commit_group;" ::: "memory");
    }

    for (int it = 0; it < NIT; it++) {
        asm volatile("cp.async.wait_group %0;" :: "n"(NS - 2) : "memory");
        __syncthreads();
        if (it + NS - 1 < NIT) issue(it + NS - 1);
        asm volatile("cp.async.commit_group;" ::: "memory");

        const char* smA = smem + (it % NS) * STAGE_BYTES;
        const char* smB = smA + A_STAGE;

        uint32_t a[2][4];
        #pragma unroll
        for (int f = 0; f < 2; f++) {
            const char* ap = smA + (wm * 32 + f * 16 + qr) * A_STRIDE + qb;
            float4 v0 = *(const float4*)(ap);
            float4 v1 = *(const float4*)(ap + 8 * A_STRIDE);
            float4 v2 = *(const float4*)(ap + 64);
            float4 v3 = *(const float4*)(ap + 8 * A_STRIDE + 64);
            a[f][0] = cvt4_e4m3(v0.x, v0.y, v0.z, v0.w);
            a[f][1] = cvt4_e4m3(v1.x, v1.y, v1.z, v1.w);
            a[f][2] = cvt4_e4m3(v2.x, v2.y, v2.z, v2.w);
            a[f][3] = cvt4_e4m3(v3.x, v3.y, v3.z, v3.w);
        }
        #pragma unroll
        for (int t = 0; t < 9; t++) {
            if (wn == 0 || t < 8) {
                const int n = (wn * 9 + t) * 8 + qr;
                uint32_t b0 = *(const uint32_t*)(smB + n * B_STRIDE + qc);
                uint32_t b1 = *(const uint32_t*)(smB + n * B_STRIDE + 16 + qc);
                #pragma unroll
                for (int f = 0; f < 2; f++) {
                    asm volatile(
                        "mma.sync.aligned.m16n8k32.row.col.f32.e4m3.e4m3.f32 "
                        "{%0,%1,%2,%3}, {%4,%5,%6,%7}, {%8,%9}, {%0,%1,%2,%3};\n"
                        : "+f"(acc[f][t][0]), "+f"(acc[f][t][1]),
                          "+f"(acc[f][t][2]), "+f"(acc[f][t][3])
                        : "r"(a[f][0]), "r"(a[f][1]), "r"(a[f][2]), "r"(a[f][3]),
                          "r"(b0), "r"(b1));
                }
            }
        }
    }

    // ---- epilogue: weighted reduction ----
    float tsum = 0.f;
    const int dq = (lane & 3) * 2;
    #pragma unroll
    for (int f = 0; f < 2; f++) {
        #pragma unroll
        for (int rr = 0; rr < 2; rr++) {
            const int i = i0 + wm * 32 + f * 16 + qr + rr * 8;
            const float* Hrow = H + ((size_t)(b * Nn + i)) * Dd;
            const float hsq_i = g_hsq[b * Nn + i];
            #pragma unroll
            for (int t = 0; t < 9; t++) {
                if (wn == 0 || t < 8) {
                    const int d0 = (wn * 9 + t) * 8 + dq;
                    float c0 = acc[f][t][rr * 2 + 0];
                    float c1 = acc[f][t][rr * 2 + 1];
                    float w0, w1;
                    if (d0 < 128)       { w0 = -2.f * Hrow[d0]; w1 = -2.f * Hrow[d0 + 1]; }
                    else if (d0 == 128) { w0 = 1.f;             w1 = hsq_i + 128.f; }
                    else                { w0 = 0.f;             w1 = 0.f; }
                    tsum += c0 * w0 + c1 * w1;
                }
            }
        }
    }
    #pragma unroll
    for (int o = 16; o; o >>= 1) tsum += __shfl_xor_sync(0xFFFFFFFFu, tsum, o);
    if (lane == 0) s_red[wid] = tsum;
    __syncthreads();
    if (tid == 0) {
        float bs = 0.f;
        #pragma unroll
        for (int x = 0; x < 8; x++) bs += s_red[x];
        g_part[(b * (Nn / TM) + mt) * KSPLIT + ks] = bs;
        __threadfence();
        int c = atomicAdd(&g_done, 1);
        s_last = (c == NBLK - 1);
    }
    __syncthreads();

    // ---- last CTA: deterministic final reduction ----
    if (s_last) {
        __shared__ float s[NBLK];
        s[tid] = *((volatile float*)&g_part[tid]);
        __syncthreads();
        #pragma unroll
        for (int o = NBLK / 2; o; o >>= 1) {
            if (tid < o) s[tid] += s[tid + o];
            __syncthreads();
        }
        if (tid == 0) out[0] = s[0] / (float)(Bq * Nn);
    }
}

// ---------------------------------------------------------------------------
extern "C" void kernel_launch(void* const* d_in, const int* in_sizes, int n_in,
                              void* d_out, int out_size) {
    const float* adj = (const float*)d_in[0];
    const float* emb = (const float*)d_in[1];

    static bool attr_done = false;
    if (!attr_done) {
        cudaFuncSetAttribute(k_main, cudaFuncAttributeMaxDynamicSharedMemorySize,
                             SMEM_BYTES);
        attr_done = true;
    }

    dim3 gp(Nn / 32, Bq);
    k_prep<<<gp, 256>>>(emb);
    dim3 gm(KSPLIT, Nn / TM, Bq);
    k_main<<<gm, 256, SMEM_BYTES>>>(adj, emb, (float*)d_out);
}